// round 10
// baseline (speedup 1.0000x reference)
#include <cuda_runtime.h>
#include <cstdint>

#define ROWS 131072
#define COLS 256
#define NM   128
#define WPB  8                    // warps per block (one row per warp)
#define THREADS (WPB * 32)

__device__ __forceinline__ uint32_t smem_u32(const void* p) {
    uint32_t a;
    asm("{ .reg .u64 t; cvta.to.shared.u64 t, %1; cvt.u32.u64 %0, t; }"
        : "=r"(a) : "l"(p));
    return a;
}

__device__ __forceinline__ void bulk_store(void* gmem, uint32_t smem, uint32_t bytes) {
    asm volatile("cp.async.bulk.global.shared::cta.bulk_group [%0], [%1], %2;"
                 :: "l"(gmem), "r"(smem), "r"(bytes) : "memory");
}

// Output = concat(masked_data, masked_indices, unmasked_data, unmasked_indices),
// each [ROWS, 128] row-major f32.
__global__ void __launch_bounds__(THREADS)
masker_kernel(const float* __restrict__ x,
              const int*   __restrict__ perm,
              float* __restrict__ out) {
    const int warp_id = threadIdx.x >> 5;
    const int lane    = threadIdx.x & 31;
    const int row     = blockIdx.x * WPB + warp_id;

    __shared__ __align__(16) float stage[WPB][3 * NM];   // [mi | ud | ui]

    // ---- global loads, front-batched ----
    const int4*   prow  = reinterpret_cast<const int4*>(perm + (size_t)row * COLS);
    const float4* xrow4 = reinterpret_cast<const float4*>(x + (size_t)row * COLS);
    int4   mh = prow[lane];         // masked half of permutation (first 128)
    float4 xa = xrow4[lane];        // x[4*lane .. 4*lane+3]
    float4 xb = xrow4[lane + 32];   // x[128+4*lane ..]

    // ---- build 256-bit membership bitmap in registers ----
    unsigned local[8] = {0, 0, 0, 0, 0, 0, 0, 0};
    {
        const int vs[4] = {mh.x, mh.y, mh.z, mh.w};
#pragma unroll
        for (int j = 0; j < 4; j++) {
            const int v = vs[j];
            const unsigned b = 1u << (v & 31);
            const int w = v >> 5;
#pragma unroll
            for (int ww = 0; ww < 8; ww++)
                local[ww] |= (w == ww) ? b : 0u;
        }
    }
    unsigned mask[8];
#pragma unroll
    for (int w = 0; w < 8; w++)
        mask[w] = __reduce_or_sync(0xffffffffu, local[w]);

    int base[8];
    int acc = 0;
#pragma unroll
    for (int w = 0; w < 8; w++) { base[w] = acc; acc += __popc(mask[w]); }

    float* smi = stage[warp_id];
    float* sud = stage[warp_id] + NM;
    float* sui = stage[warp_id] + 2 * NM;

    // lane-owned word select (w0 = lane>>3, w1 = w0+4)
    const bool hi = (lane & 16) != 0;
    const bool md = (lane & 8)  != 0;
    const unsigned mw0 = hi ? (md ? mask[3] : mask[2]) : (md ? mask[1] : mask[0]);
    const int      b0  = hi ? (md ? base[3] : base[2]) : (md ? base[1] : base[0]);
    const unsigned mw1 = hi ? (md ? mask[7] : mask[6]) : (md ? mask[5] : mask[4]);
    const int      b1  = hi ? (md ? base[7] : base[6]) : (md ? base[5] : base[4]);

    const float xv0[4] = {xa.x, xa.y, xa.z, xa.w};
    const float xv1[4] = {xb.x, xb.y, xb.z, xb.w};

    // ---- rank + scatter into stage, x straight from registers ----
#pragma unroll
    for (int j = 0; j < 4; j++) {
        const int c   = 4 * lane + j;
        const int bit = c & 31;
        const int mrank = b0 + __popc(mw0 & ((1u << bit) - 1u));
        if ((mw0 >> bit) & 1u) {
            smi[mrank] = (float)c;
        } else {
            const int urank = c - mrank;
            sud[urank] = xv0[j];
            sui[urank] = (float)c;
        }
    }
#pragma unroll
    for (int j = 0; j < 4; j++) {
        const int c   = 128 + 4 * lane + j;
        const int bit = c & 31;
        const int mrank = b1 + __popc(mw1 & ((1u << bit) - 1u));
        if ((mw1 >> bit) & 1u) {
            smi[mrank] = (float)c;
        } else {
            const int urank = c - mrank;
            sud[urank] = xv1[j];
            sui[urank] = (float)c;
        }
    }

    // ---- masked_data zeros: direct coalesced STG.128 (data is in registers) ----
    const size_t seg = (size_t)ROWS * NM;
    reinterpret_cast<float4*>(out + (size_t)row * NM)[lane] =
        make_float4(0.f, 0.f, 0.f, 0.f);

    // ---- bulk-async store of the three staged segments (512 B each) ----
    __syncwarp();
    if (lane == 0) {
        asm volatile("fence.proxy.async.shared::cta;" ::: "memory");
        const uint32_t s = smem_u32(smi);
        bulk_store(out + seg     + (size_t)row * NM, s,            NM * 4);
        bulk_store(out + 2 * seg + (size_t)row * NM, s + NM * 4,   NM * 4);
        bulk_store(out + 3 * seg + (size_t)row * NM, s + 2 * NM * 4, NM * 4);
        asm volatile("cp.async.bulk.commit_group;" ::: "memory");
        asm volatile("cp.async.bulk.wait_group 0;" ::: "memory");
    }
}

extern "C" void kernel_launch(void* const* d_in, const int* in_sizes, int n_in,
                              void* d_out, int out_size) {
    const float* x    = (const float*)d_in[0];
    const int*   perm = (const int*)d_in[1];
    float* out = (float*)d_out;

    masker_kernel<<<ROWS / WPB, THREADS>>>(x, perm, out);
}